// round 8
// baseline (speedup 1.0000x reference)
#include <cuda_runtime.h>
#include <math.h>

#define N_NODES 100000
#define N_EDGES 1000000
#define D_NODE 64
#define D_EDGE 16
#define NUM_PAR 80
#define HIDDEN 160

#define NODE_BLOCKS 592
#define NODE_THREADS 512          // 16 warps; 2 nodes per warp per iteration

#define EDGE_THREADS 256          // 8 warps
#define EDGE_CPW 4                // chunks (of 32 edges) per warp
#define EDGES_PER_BLOCK (8 * 32 * EDGE_CPW)   // 1024
#define EDGE_BLOCKS ((N_EDGES + EDGES_PER_BLOCK - 1) / EDGES_PER_BLOCK)

// Scratch (allocation-free rule).
__device__ float g_p[N_NODES];
__device__ float g_w16[D_EDGE];   // collapsed w[64:80], written by node_kernel blk 0
__device__ float g_c;             // collapsed bias,    written by node_kernel blk 0

// Warp-cooperative collapsed weight for one row r of W1:
//   w[r] = sum_j W1[r,j] * W2[j], lane-parallel over j (5 strides of 32).
__device__ __forceinline__ float collapse_row(const float* __restrict__ W1,
                                              const float* __restrict__ w2reg,
                                              int r, int lane) {
    const float* row = W1 + r * HIDDEN;
    float s = 0.f;
    #pragma unroll
    for (int k = 0; k < 5; k++)
        s = fmaf(__ldg(row + lane + 32 * k), w2reg[k], s);
    #pragma unroll
    for (int o = 16; o > 0; o >>= 1)
        s += __shfl_xor_sync(0xFFFFFFFFu, s, o);
    return s;   // valid in all lanes
}

// ---------------------------------------------------------------------------
// Kernel A: node projections p[n] = dot(x[n], w[0:64]).
// Warps 0-7: recompute w[0:64] per block (L2-resident after wave 1).
// Block 0 only, warps 8-15: also compute w[64:80] and c into globals for the
// edge kernel (visible at the next launch; removes its prologue entirely).
// Main loop: warp handles 2 nodes/iter; lane loads one float4 (512B/warp,
// coalesced), 16-lane shuffle-tree reduction.
// ---------------------------------------------------------------------------
__global__ __launch_bounds__(NODE_THREADS)
void node_kernel(const float* __restrict__ x,
                 const float* __restrict__ W1,
                 const float* __restrict__ b1,
                 const float* __restrict__ W2,
                 const float* __restrict__ b2) {
    __shared__ float sw[D_NODE];
    int t = threadIdx.x;
    int warp = t >> 5;
    int lane = t & 31;

    if (warp < 8) {
        float w2[5];
        #pragma unroll
        for (int k = 0; k < 5; k++) w2[k] = __ldg(W2 + lane + 32 * k);
        #pragma unroll
        for (int rr = 0; rr < 8; rr++) {
            int r = warp * 8 + rr;
            float s = collapse_row(W1, w2, r, lane);
            if (lane == 0) sw[r] = s;
        }
    } else if (blockIdx.x == 0) {
        // Warps 8-15: edge-side constants. Warp (8+i) -> rows 64+2i, 65+2i.
        float w2[5];
        #pragma unroll
        for (int k = 0; k < 5; k++) w2[k] = __ldg(W2 + lane + 32 * k);
        int i = warp - 8;
        #pragma unroll
        for (int rr = 0; rr < 2; rr++) {
            float s = collapse_row(W1, w2, D_NODE + 2 * i + rr, lane);
            if (lane == 0) g_w16[2 * i + rr] = s;
        }
        if (warp == 8) {   // c = b1 . W2 + b2
            float s = 0.f;
            #pragma unroll
            for (int k = 0; k < 5; k++)
                s = fmaf(__ldg(b1 + lane + 32 * k), w2[k], s);
            #pragma unroll
            for (int o = 16; o > 0; o >>= 1)
                s += __shfl_xor_sync(0xFFFFFFFFu, s, o);
            if (lane == 0) g_c = s + __ldg(b2);
        }
    }
    __syncthreads();

    int half = lane >> 4;        // which of the warp's 2 nodes
    int q    = lane & 15;        // float4 slot within the node row
    float w0 = sw[q * 4 + 0];
    float w1 = sw[q * 4 + 1];
    float w2r = sw[q * 4 + 2];
    float w3 = sw[q * 4 + 3];

    const float4* x4 = (const float4*)x;
    const int stride = NODE_BLOCKS * (NODE_THREADS / 32) * 2;

    for (int node = blockIdx.x * ((NODE_THREADS / 32) * 2) + warp * 2 + half;
         node < N_NODES; node += stride) {
        float4 v = __ldg(x4 + (size_t)node * 16 + q);
        float s = fmaf(v.x, w0, fmaf(v.y, w1, fmaf(v.z, w2r, v.w * w3)));
        #pragma unroll
        for (int o = 8; o > 0; o >>= 1)
            s += __shfl_xor_sync(0xFFFFFFFFu, s, o);
        if (q == 0) g_p[node] = s;
    }
}

// ---------------------------------------------------------------------------
// Kernel B: per-edge  z = p[src] + p[dst] + ea[e].w[64:80] + c;  sigmoid(z).
// Warp-cooperative layout, chunks of 32 edges per warp:
//   phase 1: lane l loads src/dst of edge cb+l (coalesced low-word loads,
//            works for int32 and int64<2^31 via stride mult), gathers
//            ps = p[src]+p[dst] (the only scattered traffic).
//   phase 2 (x4 rounds): warp loads 32 CONSECUTIVE float4s = 8 full edge
//            rows (128B/wavefront, the L1 floor). Quad of lanes holds one
//            edge; partial dot vs its 4 weights, 2x shfl_xor reduce, ps
//            fetched by one shuffle, lane 4m writes out[cb+8r+m].
// Next chunk's index+gather loads are issued before current chunk's rounds.
// No smem, no block sync; ~30 regs -> 6 blocks/SM (48 warps).
// ---------------------------------------------------------------------------
__global__ __launch_bounds__(EDGE_THREADS, 6)
void edge_kernel(const void* __restrict__ ei_raw,
                 const float* __restrict__ ea,
                 float* __restrict__ out) {
    int t = threadIdx.x;
    int warp = t >> 5;
    int lane = t & 31;

    // Per-warp dtype probe: 32 entries as int64 all in [0,N_NODES) <=> int64
    // (int32 data would need 32 zero hi-words: P ~ 1e-160). L1-hot after wave 1.
    const long long* ei64 = (const long long*)ei_raw;
    long long pv = __ldg(ei64 + lane);
    unsigned bal = __ballot_sync(0xFFFFFFFFu, pv >= 0 && pv < N_NODES);
    const int mult = (bal == 0xFFFFFFFFu) ? 2 : 1;

    // Each lane needs only the 4 weights of its quad-component j = lane&3.
    int j = lane & 3;
    float rw0 = g_w16[4 * j + 0];
    float rw1 = g_w16[4 * j + 1];
    float rw2 = g_w16[4 * j + 2];
    float rw3 = g_w16[4 * j + 3];
    const float c = g_c;

    const int*    eidx = (const int*)ei_raw;   // low 4B hold the value (LE)
    const float4* ea4  = (const float4*)ea;

    const int warp_base = (blockIdx.x * 8 + warp) * (32 * EDGE_CPW);

    // Prefetch chunk 0 indices + gathers.
    float ps_cur;
    {
        int e  = warp_base + lane;
        int ec = e < N_EDGES ? e : (N_EDGES - 1);
        int s  = __ldg(eidx + (size_t)mult * ec);
        int d  = __ldg(eidx + (size_t)mult * ((size_t)N_EDGES + ec));
        ps_cur = g_p[s] + g_p[d];
    }

    #pragma unroll
    for (int chunk = 0; chunk < EDGE_CPW; chunk++) {
        const int cb = warp_base + chunk * 32;

        // Prefetch next chunk's scattered work.
        float ps_next = 0.f;
        if (chunk + 1 < EDGE_CPW) {
            int e  = cb + 32 + lane;
            int ec = e < N_EDGES ? e : (N_EDGES - 1);
            int s  = __ldg(eidx + (size_t)mult * ec);
            int d  = __ldg(eidx + (size_t)mult * ((size_t)N_EDGES + ec));
            ps_next = g_p[s] + g_p[d];
        }

        #pragma unroll
        for (int r = 0; r < 4; r++) {
            // 32 consecutive float4s cover edges [cb+8r, cb+8r+8).
            long fidx = (long)cb * 4 + r * 32 + lane;
            float4 a;
            if (fidx < (long)N_EDGES * 4) a = __ldg(ea4 + fidx);
            else                          a = make_float4(0.f, 0.f, 0.f, 0.f);

            float s = fmaf(a.x, rw0, fmaf(a.y, rw1, fmaf(a.z, rw2, a.w * rw3)));
            s += __shfl_xor_sync(0xFFFFFFFFu, s, 1);
            s += __shfl_xor_sync(0xFFFFFFFFu, s, 2);

            // ps of edge cb+8r+m lives in lane 8r+m; writer lane is 4m.
            float pse = __shfl_sync(0xFFFFFFFFu, ps_cur, 8 * r + (lane >> 2));

            if ((lane & 3) == 0) {
                int e = cb + 8 * r + (lane >> 2);
                if (e < N_EDGES) {
                    float z = pse + c + s;
                    out[e] = 1.0f / (1.0f + __expf(-z));
                }
            }
        }
        ps_cur = ps_next;
    }
}

extern "C" void kernel_launch(void* const* d_in, const int* in_sizes, int n_in,
                              void* d_out, int out_size) {
    // metadata order: x, edge_index, edge_attr, W1, b1, W2, b2
    const float* x  = (const float*)d_in[0];
    const void*  ei = d_in[1];
    const float* ea = (const float*)d_in[2];
    const float* W1 = (const float*)d_in[3];
    const float* b1 = (const float*)d_in[4];
    const float* W2 = (const float*)d_in[5];
    const float* b2 = (const float*)d_in[6];
    float* out = (float*)d_out;

    node_kernel<<<NODE_BLOCKS, NODE_THREADS>>>(x, W1, b1, W2, b2);
    edge_kernel<<<EDGE_BLOCKS, EDGE_THREADS>>>(ei, ea, out);
}